// round 1
// baseline (speedup 1.0000x reference)
#include <cuda_runtime.h>

#define S 64
#define PATCH 56
// g_perm[b][l] = k : source tile index for dest tile l, for permutation P_b
__device__ int g_perm[32][S];

// One block per batch element (64 threads = 1 thread per column).
// Computes softmax over axis 0, then greedy assignment:
// repeatedly take global argmax among unused rows/cols.
// Incremental: maintain per-column best over unmasked rows; only columns whose
// best row just got masked need a rescan.
__global__ void perm_kernel(const float* __restrict__ params,
                            float* __restrict__ result_out,
                            const int* __restrict__ p_seq,
                            const int* __restrict__ p_bsz,
                            int B) {
    int b = blockIdx.x;
    int tid = threadIdx.x;            // 0..63
    int start = (p_seq && p_bsz) ? (p_seq[0] * p_bsz[0]) : 64;
    const float* p = params + (size_t)(start + b) * S * S;

    __shared__ float m[S * S];
    __shared__ float colv[S];
    __shared__ int   colr[S];         // -1 marks a used (selected) column
    __shared__ unsigned long long rowUsed;
    __shared__ float wval[2];
    __shared__ int   widx[2];
    __shared__ int   s_win;
    __shared__ int   perm[S];         // perm[j] = selected row for column j

    for (int i = tid; i < S * S; i += 64) m[i] = p[i];
    __syncthreads();

    // softmax over axis 0 (rows) for column `tid`, and initial column max
    {
        int j = tid;
        float mx = -1e30f;
        for (int i = 0; i < S; i++) mx = fmaxf(mx, m[i * S + j]);
        float sum = 0.f;
        for (int i = 0; i < S; i++) {
            float e = expf(m[i * S + j] - mx);
            m[i * S + j] = e;
            sum += e;
        }
        float inv = 1.f / sum;
        float best = -1.f; int br = 0;
        for (int i = 0; i < S; i++) {
            float v = m[i * S + j] * inv;
            m[i * S + j] = v;
            if (v > best) { best = v; br = i; }
        }
        colv[j] = best; colr[j] = br;
    }
    if (tid == 0) rowUsed = 0ULL;
    __syncthreads();

    for (int t = 0; t < S; t++) {
        // candidate for this column (invalid if already selected)
        float v = (colr[tid] < 0) ? -1.f : colv[tid];
        int   j = tid;
        // warp argmax (two warps)
        #pragma unroll
        for (int off = 16; off > 0; off >>= 1) {
            float ov = __shfl_down_sync(0xffffffffu, v, off);
            int   oj = __shfl_down_sync(0xffffffffu, j, off);
            if (ov > v) { v = ov; j = oj; }
        }
        if ((tid & 31) == 0) { wval[tid >> 5] = v; widx[tid >> 5] = j; }
        __syncthreads();
        if (tid == 0) {
            int jw = (wval[1] > wval[0]) ? widx[1] : widx[0];
            int iw = colr[jw];
            perm[jw] = iw;
            colr[jw] = -1;
            rowUsed |= (1ULL << iw);
            s_win = iw;
        }
        __syncthreads();
        int iw = s_win;
        // rescan columns whose best row was just masked
        if (colr[tid] == iw) {
            unsigned long long ru = rowUsed;
            float best = -1.f; int br = -1;
            for (int i = 0; i < S; i++) {
                if ((ru >> i) & 1ULL) continue;
                float vv = m[i * S + tid];
                if (vv > best) { best = vv; br = i; }
            }
            colv[tid] = best; colr[tid] = br;
        }
        __syncthreads();
    }

    // persist permutation for the shuffle kernel
    g_perm[b][tid] = perm[tid];

    // write `result` (broadcast across 3 channels, batch-reversed)
    int b_out = B - 1 - b;
    float* r = result_out + (size_t)b_out * 3 * S * S;
    for (int idx = tid; idx < S * S; idx += 64) {
        int i = idx >> 6, j = idx & 63;
        float v = (perm[j] == i) ? 1.0f : 0.0f;
        r[idx] = v;
        r[S * S + idx] = v;
        r[2 * S * S + idx] = v;
    }
}

// One block per (channel-image, dest-tile). Copies a 56x56 float tile.
// blockDim = (14, 16): 14 float4 per tile row, 16 rows in flight.
__global__ void shuffle_kernel(const float* __restrict__ x,
                               float* __restrict__ out, int B) {
    int l  = blockIdx.x;          // dest tile 0..63
    int bc = blockIdx.y;          // 0..3B-1
    int b  = bc / 3;
    int k  = g_perm[B - 1 - b][l];   // out batch b uses P_{B-1-b}
    int s1 = l >> 3, s2 = l & 7;
    int k1 = k >> 3, k2 = k & 7;

    const float4* src = (const float4*)(x   + ((size_t)bc * 448 + (size_t)k1 * PATCH) * 448 + k2 * PATCH);
    float4*       dst = (float4*)      (out + ((size_t)bc * 448 + (size_t)s1 * PATCH) * 448 + s2 * PATCH);

    int tx = threadIdx.x;         // 0..13
    for (int r = threadIdx.y; r < PATCH; r += 16) {
        dst[r * 112 + tx] = src[r * 112 + tx];
    }
}

extern "C" void kernel_launch(void* const* d_in, const int* in_sizes, int n_in,
                              void* d_out, int out_size) {
    const float* x      = (const float*)d_in[0];
    const float* params = (const float*)d_in[1];
    const int* p_seq = (n_in > 2) ? (const int*)d_in[2] : nullptr;
    const int* p_bsz = (n_in > 3) ? (const int*)d_in[3] : nullptr;

    int B = in_sizes[0] / (3 * 448 * 448);   // 32
    float* out        = (float*)d_out;
    float* result_out = out + (size_t)B * 3 * 448 * 448;

    perm_kernel<<<B, 64>>>(params, result_out, p_seq, p_bsz, B);

    dim3 bd(14, 16);
    dim3 gd(64, 3 * B);
    shuffle_kernel<<<gd, bd>>>(x, out, B);
}

// round 4
// speedup vs baseline: 1.4337x; 1.4337x over previous
#include <cuda_runtime.h>

#define S 64
#define PATCH 56
#define FULL 0xffffffffu

// g_perm[b][l] = k : source tile index for dest tile l, for permutation P_b
__device__ int g_perm[32][S];

// One block = one warp = one batch element.
// softmax over axis 0, then greedy global-argmax assignment (64 sequential picks).
// Each lane owns columns `lane` and `lane+32`.
__global__ void perm_kernel(const float* __restrict__ params,
                            float* __restrict__ result_out,
                            const int* __restrict__ p_seq,
                            const int* __restrict__ p_bsz,
                            int B) {
    int b = blockIdx.x;
    int lane = threadIdx.x;           // 0..31
    int start = (p_seq && p_bsz) ? (p_seq[0] * p_bsz[0]) : 64;
    const float* p = params + (size_t)(start + b) * S * S;

    __shared__ float m[S * S];
    __shared__ int   perm[S];         // perm[j] = selected row for column j

    // load 16KB matrix (32 float4 per lane)
    {
        float4* m4 = (float4*)m;
        const float4* p4 = (const float4*)p;
        #pragma unroll
        for (int q = 0; q < 32; q++) m4[lane + q * 32] = p4[lane + q * 32];
    }
    __syncwarp();

    // softmax over rows for my 2 columns; track per-column best (val,row)
    float v0, v1; int r0, r1;
    {
        int j0 = lane, j1 = lane + 32;
        float mx0 = -1e30f, mx1 = -1e30f;
        #pragma unroll 4
        for (int i = 0; i < S; i++) {
            mx0 = fmaxf(mx0, m[i * S + j0]);
            mx1 = fmaxf(mx1, m[i * S + j1]);
        }
        float s0 = 0.f, s1 = 0.f;
        #pragma unroll 4
        for (int i = 0; i < S; i++) {
            float e0 = __expf(m[i * S + j0] - mx0);  // fast exp; rel err ~1e-6, far below gaps
            float e1 = __expf(m[i * S + j1] - mx1);
            m[i * S + j0] = e0; s0 += e0;
            m[i * S + j1] = e1; s1 += e1;
        }
        float inv0 = 1.f / s0, inv1 = 1.f / s1;
        v0 = -1.f; v1 = -1.f; r0 = 0; r1 = 0;
        #pragma unroll 4
        for (int i = 0; i < S; i++) {
            float a0 = m[i * S + j0] * inv0;
            float a1 = m[i * S + j1] * inv1;
            m[i * S + j0] = a0;
            m[i * S + j1] = a1;
            if (a0 > v0) { v0 = a0; r0 = i; }
            if (a1 > v1) { v1 = a1; r1 = i; }
        }
    }
    __syncwarp();

    for (int t = 0; t < S; t++) {
        // candidate = larger of my two live columns.
        // Pack (float bits with low 6 bits cleared) | column index into one u32 key.
        // Positive floats order as u32; distinct candidate gaps >> 2^-12 so the
        // stolen mantissa bits never change the winner.
        unsigned c0 = (r0 >= 0) ? (__float_as_uint(v0) & ~0x3Fu) | (unsigned)lane        : 0u;
        unsigned c1 = (r1 >= 0) ? (__float_as_uint(v1) & ~0x3Fu) | (unsigned)(lane + 32) : 0u;
        unsigned key = (c0 >= c1) ? c0 : c1;
        // butterfly max across the warp
        #pragma unroll
        for (int off = 16; off > 0; off >>= 1) {
            unsigned ok = __shfl_xor_sync(FULL, key, off);
            key = (ok > key) ? ok : key;
        }
        int jw = (int)(key & 0x3Fu);          // winning column
        int wl = jw & 31;                     // its owner lane
        bool winHi = (jw >= 32);
        // fetch winning row from the owner lane
        int myi = winHi ? r1 : r0;
        int iw = __shfl_sync(FULL, myi, wl);

        if (lane == wl) {
            perm[jw] = iw;
            if (winHi) r1 = -1; else r0 = -1;
        }
        // mask row iw (all lanes cover the 64 columns)
        m[iw * S + lane] = -1.f;
        m[iw * S + lane + 32] = -1.f;
        __syncwarp();

        // rescan my columns whose best row just died (masked entries are -1)
        if (r0 == iw) {
            int j = lane;
            float b0=-1.f,b1=-1.f,b2=-1.f,b3=-1.f; int i0=0,i1=1,i2=2,i3=3;
            #pragma unroll
            for (int i = 0; i < S; i += 4) {
                float a0=m[(i  )*S+j], a1=m[(i+1)*S+j], a2=m[(i+2)*S+j], a3=m[(i+3)*S+j];
                if (a0>b0){b0=a0;i0=i;}   if (a1>b1){b1=a1;i1=i+1;}
                if (a2>b2){b2=a2;i2=i+2;} if (a3>b3){b3=a3;i3=i+3;}
            }
            if (b1>b0){b0=b1;i0=i1;} if (b3>b2){b2=b3;i2=i3;}
            if (b2>b0){b0=b2;i0=i2;}
            v0=b0; r0=i0;
        }
        if (r1 == iw) {
            int j = lane + 32;
            float b0=-1.f,b1=-1.f,b2=-1.f,b3=-1.f; int i0=0,i1=1,i2=2,i3=3;
            #pragma unroll
            for (int i = 0; i < S; i += 4) {
                float a0=m[(i  )*S+j], a1=m[(i+1)*S+j], a2=m[(i+2)*S+j], a3=m[(i+3)*S+j];
                if (a0>b0){b0=a0;i0=i;}   if (a1>b1){b1=a1;i1=i+1;}
                if (a2>b2){b2=a2;i2=i+2;} if (a3>b3){b3=a3;i3=i+3;}
            }
            if (b1>b0){b0=b1;i0=i1;} if (b3>b2){b2=b3;i2=i3;}
            if (b2>b0){b0=b2;i0=i2;}
            v1=b0; r1=i0;
        }
        __syncwarp();
    }

    // publish perm for the shuffle kernel
    g_perm[b][lane]      = perm[lane];
    g_perm[b][lane + 32] = perm[lane + 32];

    // write `result` (0/1 permutation matrix, x3 channels, batch-reversed)
    int b_out = B - 1 - b;
    float* r = result_out + (size_t)b_out * 3 * S * S;
    float4* r4 = (float4*)r;
    const int4* pm4 = (const int4*)perm;
    #pragma unroll
    for (int q = 0; q < 32; q++) {
        int pos = lane + q * 32;            // float4 index within S*S
        int i = pos >> 4;                   // row
        int4 pr = pm4[pos & 15];            // perm[j..j+3]
        float4 v;
        v.x = (pr.x == i) ? 1.f : 0.f;
        v.y = (pr.y == i) ? 1.f : 0.f;
        v.z = (pr.z == i) ? 1.f : 0.f;
        v.w = (pr.w == i) ? 1.f : 0.f;
        r4[pos] = v;
        r4[pos + 1024] = v;
        r4[pos + 2048] = v;
    }
}

// One block per (channel-image, dest-tile). Copies a 56x56 float tile.
// 196 threads, each does 4 independent float4 loads then 4 stores (MLP=4).
__global__ void __launch_bounds__(196) shuffle_kernel(const float* __restrict__ x,
                                                      float* __restrict__ out, int B) {
    int l  = blockIdx.x;             // dest tile 0..63
    int bc = blockIdx.y;             // 0..3B-1
    int b  = bc / 3;
    int k  = g_perm[B - 1 - b][l];
    int s1 = l >> 3, s2 = l & 7;
    int k1 = k >> 3, k2 = k & 7;

    const float4* src = (const float4*)(x   + ((size_t)bc * 448 + (size_t)k1 * PATCH) * 448 + k2 * PATCH);
    float4*       dst = (float4*)      (out + ((size_t)bc * 448 + (size_t)s1 * PATCH) * 448 + s2 * PATCH);

    int t = threadIdx.x;             // 0..195
    int f0 = t, f1 = t + 196, f2 = t + 392, f3 = t + 588;   // of 784 float4
    int o0 = (f0 / 14) * 112 + (f0 % 14);
    int o1 = (f1 / 14) * 112 + (f1 % 14);
    int o2 = (f2 / 14) * 112 + (f2 % 14);
    int o3 = (f3 / 14) * 112 + (f3 % 14);

    float4 a = __ldcs(src + o0);
    float4 c = __ldcs(src + o1);
    float4 d = __ldcs(src + o2);
    float4 e = __ldcs(src + o3);
    __stcs(dst + o0, a);
    __stcs(dst + o1, c);
    __stcs(dst + o2, d);
    __stcs(dst + o3, e);
}

extern "C" void kernel_launch(void* const* d_in, const int* in_sizes, int n_in,
                              void* d_out, int out_size) {
    const float* x      = (const float*)d_in[0];
    const float* params = (const float*)d_in[1];
    const int* p_seq = (n_in > 2) ? (const int*)d_in[2] : nullptr;
    const int* p_bsz = (n_in > 3) ? (const int*)d_in[3] : nullptr;

    int B = in_sizes[0] / (3 * 448 * 448);   // 32
    float* out        = (float*)d_out;
    float* result_out = out + (size_t)B * 3 * 448 * 448;

    perm_kernel<<<B, 32>>>(params, result_out, p_seq, p_bsz, B);

    dim3 gd(64, 3 * B);
    shuffle_kernel<<<gd, 196>>>(x, out, B);
}